// round 10
// baseline (speedup 1.0000x reference)
#include <cuda_runtime.h>
#include <cuda_bf16.h>
#include <cstdint>

#define BATCH 256
#define NN 256
#define MM 256
#define DIM 32
#define BIGF 1e8f
#define LOG2E 1.4426950408889634f
#define SBIG (1e8f * LOG2E)     // BIG in log2 domain

// dist TRANSPOSED per batch: gb[(j-1)*256 + (i-1)] = dist(i-1, j-1)
__device__ float g_dist[BATCH * NN * MM];
__device__ float g_partial[BATCH];

__device__ __forceinline__ uint32_t smem_u32(const void* p) {
    uint32_t a;
    asm("{ .reg .u64 t; cvta.to.shared.u64 t, %1; cvt.u32.u64 %0, t; }" : "=r"(a) : "l"(p));
    return a;
}
__device__ __forceinline__ void ldmx4(uint32_t* r, uint32_t addr) {
    asm volatile("ldmatrix.sync.aligned.m8n8.x4.shared.b16 {%0,%1,%2,%3}, [%4];"
                 : "=r"(r[0]), "=r"(r[1]), "=r"(r[2]), "=r"(r[3]) : "r"(addr));
}
__device__ __forceinline__ void mma16816(float* c, const uint32_t* a, uint32_t b0,
                                         uint32_t b1) {
    asm volatile(
        "mma.sync.aligned.m16n8k16.row.col.f32.bf16.bf16.f32 "
        "{%0,%1,%2,%3}, {%4,%5,%6,%7}, {%8,%9}, {%0,%1,%2,%3};"
        : "+f"(c[0]), "+f"(c[1]), "+f"(c[2]), "+f"(c[3])
        : "r"(a[0]), "r"(a[1]), "r"(a[2]), "r"(a[3]), "r"(b0), "r"(b1));
}

#define PITCHB 80

// ---------------------------------------------------------------------------
// Kernel 1: dist via mma.sync bf16 (validated; called with (y,x) swapped so
// the output is dist^T: gb[c_of_y*256 + r_of_x]).
// ---------------------------------------------------------------------------
__global__ __launch_bounds__(256) void dist_kernel(const float* __restrict__ x,
                                                   const float* __restrict__ y) {
    __shared__ __align__(16) char xs[256 * PITCHB];
    __shared__ __align__(16) char ys[256 * PITCHB];
    __shared__ float x2s[256];
    __shared__ float y2s[256];

    const int b = blockIdx.x, t = threadIdx.x;
    const int w = t >> 5, lane = t & 31;
    const float* xr = x + ((size_t)b * NN + t) * DIM;
    const float* yr = y + ((size_t)b * MM + t) * DIM;

    {
        float sx = 0.f, sy = 0.f;
#pragma unroll
        for (int q = 0; q < 8; q++) {
            float4 v = *(const float4*)(xr + q * 4);
            sx = fmaf(v.x, v.x, fmaf(v.y, v.y, fmaf(v.z, v.z, fmaf(v.w, v.w, sx))));
            uint2 wv;
            asm("cvt.rn.bf16x2.f32 %0, %1, %2;" : "=r"(wv.x) : "f"(v.y), "f"(v.x));
            asm("cvt.rn.bf16x2.f32 %0, %1, %2;" : "=r"(wv.y) : "f"(v.w), "f"(v.z));
            *(uint2*)(xs + t * PITCHB + q * 8) = wv;
            float4 u = *(const float4*)(yr + q * 4);
            sy = fmaf(u.x, u.x, fmaf(u.y, u.y, fmaf(u.z, u.z, fmaf(u.w, u.w, sy))));
            uint2 uv;
            asm("cvt.rn.bf16x2.f32 %0, %1, %2;" : "=r"(uv.x) : "f"(u.y), "f"(u.x));
            asm("cvt.rn.bf16x2.f32 %0, %1, %2;" : "=r"(uv.y) : "f"(u.w), "f"(u.z));
            *(uint2*)(ys + t * PITCHB + q * 8) = uv;
        }
        x2s[t] = sx;
        y2s[t] = sy;
    }
    __syncthreads();

    const uint32_t xsb = smem_u32(xs), ysb = smem_u32(ys);
    const int i0w = w * 32;

    uint32_t afr[2][2][4];
    {
        int rowA = i0w + (lane & 15);
        uint32_t base = xsb + rowA * PITCHB + ((lane >> 4) << 4);
#pragma unroll
        for (int rt = 0; rt < 2; rt++)
#pragma unroll
            for (int ks = 0; ks < 2; ks++)
                ldmx4(afr[rt][ks], base + rt * 16 * PITCHB + ks * 32);
    }

    float* gb = g_dist + (size_t)b * (NN * MM);
    const int rsub = lane >> 2;
    const int cpair = 2 * (lane & 3);

    for (int cg = 0; cg < 16; cg++) {
        const int c0 = cg * 16;
        uint32_t bbase = ysb + (c0 + (lane & 7) + ((lane & 16) >> 1)) * PITCHB +
                         ((lane >> 3) & 1) * 16;
        uint32_t b_k0[4], b_k1[4];
        ldmx4(b_k0, bbase);
        ldmx4(b_k1, bbase + 32);

#pragma unroll
        for (int rt = 0; rt < 2; rt++) {
            float C0[4] = {0.f, 0.f, 0.f, 0.f};
            float C1[4] = {0.f, 0.f, 0.f, 0.f};
            mma16816(C0, afr[rt][0], b_k0[0], b_k0[1]);
            mma16816(C0, afr[rt][1], b_k1[0], b_k1[1]);
            mma16816(C1, afr[rt][0], b_k0[2], b_k0[3]);
            mma16816(C1, afr[rt][1], b_k1[2], b_k1[3]);

            const int r_lo = i0w + rt * 16 + rsub;
            const float x2lo = x2s[r_lo], x2hi = x2s[r_lo + 8];
#pragma unroll
            for (int nt = 0; nt < 2; nt++) {
                const float* C = nt ? C1 : C0;
                const int cc = c0 + nt * 8 + cpair;
                float2 yy = *(const float2*)(y2s + cc);
                float2 olo, ohi;
                olo.x = fmaxf(fmaf(-2.f, C[0], x2lo + yy.x), 0.f);
                olo.y = fmaxf(fmaf(-2.f, C[1], x2lo + yy.y), 0.f);
                ohi.x = fmaxf(fmaf(-2.f, C[2], x2hi + yy.x), 0.f);
                ohi.y = fmaxf(fmaf(-2.f, C[3], x2hi + yy.y), 0.f);
                *(float2*)(gb + r_lo * 256 + cc) = olo;
                *(float2*)(gb + (r_lo + 8) * 256 + cc) = ohi;
            }
        }
    }
}

// ---------------------------------------------------------------------------
// Kernel 2: deferred-log (A,s) wavefront DP, column-pair ownership.
// 256 CTAs (1 batch each) x 160 threads (5 warps). Lane l of warp w owns
// columns jA=60w+1+2l, jB=jA+1. Warps overlap 4 columns (lanes 0,1 of
// w>=1 redundant, refreshed from smem every 4-diag group, double-buffered).
// D = ln2*A - ln(s); recurrence: m=min(A_k); s'=sum s_k*exp2(m-A_k);
// A'=dq*log2e + m. Log applied once at the end.
// ---------------------------------------------------------------------------
#define NWARP 5
#define NTD (NWARP * 32)

__device__ __forceinline__ int clampi(int v) { return v < 0 ? 0 : (v > 255 ? 255 : v); }

__global__ __launch_bounds__(NTD) void dtw_kernel() {
    __shared__ float bnd[2 * 4 * 20];   // [parity][boundary][18 used]
    const int b = blockIdx.x, t = threadIdx.x;
    const int w = t >> 5, l = t & 31;
    const int jA = 60 * w + 1 + 2 * l, jB = jA + 1;
    const bool w0l0 = (w == 0 && l == 0);

    const float* gT = g_dist + (size_t)b * (NN * MM);
    const float* colA = gT + (size_t)(jA - 1 < 255 ? jA - 1 : 255) * 256;
    const float* colB = gT + (size_t)(jB - 1 < 255 ? jB - 1 : 255) * 256;

    // state: (A, s) pairs in log2 domain
    float vA_A = SBIG, vA_s = 1.f;    // col jA, diag p-1
    float vB_A = SBIG, vB_s = 1.f;    // col jB, diag p-1
    float pvA_A = SBIG, pvA_s = 1.f;  // col jA, diag p-2
    float pvB_A = SBIG, pvB_s = 1.f;  // col jB, diag p-2
    float dg_A = w0l0 ? 0.f : SBIG, dg_s = 1.f;  // col jA-1, diag p-2

    // preload dq (scaled by log2e) for group 0
    float cqA[4], cqB[4], nqA[4], nqB[4];
#pragma unroll
    for (int s = 0; s < 4; s++) {
        cqA[s] = colA[clampi(1 + s - jA)] * LOG2E;
        cqB[s] = colB[clampi(1 + s - jB)] * LOG2E;
    }

    for (int g = 0; g < 128; ++g) {
        // import refreshed state (published at end of group g-1)
        if (g > 0 && w >= 1 && l < 2) {
            const float* B = bnd + (((g - 1) & 1) * 4 + (w - 1)) * 20;
            if (l == 0) {
                vA_A = B[2]; vA_s = B[3]; vB_A = B[4]; vB_s = B[5];
                pvA_A = B[6]; pvA_s = B[7]; dg_A = B[0]; dg_s = B[1];
            } else {
                vA_A = B[10]; vA_s = B[11]; vB_A = B[12]; vB_s = B[13];
                pvA_A = B[14]; pvA_s = B[15]; dg_A = B[8]; dg_s = B[9];
            }
        }

        // prefetch next group's dq
        {
            const int base = 4 * (g + 1) + 1;
#pragma unroll
            for (int s = 0; s < 4; s++) {
                nqA[s] = colA[clampi(base + s - jA)] * LOG2E;
                nqB[s] = colB[clampi(base + s - jB)] * LOG2E;
            }
        }

        const int pbase = 2 + 4 * g;
#pragma unroll
        for (int s = 0; s < 4; s++) {
            const int p = pbase + s;
            float lfA = __shfl_up_sync(0xffffffffu, vB_A, 1);
            float lfS = __shfl_up_sync(0xffffffffu, vB_s, 1);
            if (w0l0) { lfA = SBIG; lfS = 1.f; }

            // cell A (col jA): up=(vA), left=(lf), diag=(dg)
            float mA = fminf(fminf(vA_A, lfA), dg_A);
            float euA = exp2f(mA - vA_A);
            float elA = exp2f(mA - lfA);
            float edA = exp2f(mA - dg_A);
            float sA = fmaf(vA_s, euA, fmaf(lfS, elA, dg_s * edA));
            float nAA = cqA[s] + mA;

            // cell B (col jB): up=(vB), left=(vA old), diag=(pvA)
            float mB = fminf(fminf(vB_A, vA_A), pvA_A);
            float euB = exp2f(mB - vB_A);
            float elB = exp2f(mB - vA_A);
            float edB = exp2f(mB - pvA_A);
            float sB = fmaf(vB_s, euB, fmaf(vA_s, elB, pvA_s * edB));
            float nBA = cqB[s] + mB;

            const bool actA = (jA <= 256) && ((unsigned)(p - jA - 1) < 256u);
            const bool actB = (jB <= 256) && ((unsigned)(p - jB - 1) < 256u);

            // rotate state
            pvA_A = vA_A; pvA_s = vA_s;
            pvB_A = vB_A; pvB_s = vB_s;
            dg_A = lfA; dg_s = lfS;
            if (w0l0) { dg_A = SBIG; dg_s = 1.f; }   // D[i-1][0] = BIG for i>=2
            vA_A = actA ? nAA : vA_A;  vA_s = actA ? sA : vA_s;
            vB_A = actB ? nBA : vB_A;  vB_s = actB ? sB : vB_s;
        }

        // renorm (exact: s *= 2^-20, A -= 20)
        {
            if (vA_s > 1048576.f) { vA_s *= 9.5367431640625e-7f; vA_A -= 20.f; }
            if (vB_s > 1048576.f) { vB_s *= 9.5367431640625e-7f; vB_A -= 20.f; }
        }

        // publish boundary state (lanes 29-31 of warps 0-3)
        if (w < 4 && l >= 29) {
            float* B = bnd + ((g & 1) * 4 + w) * 20;
            if (l == 29) { B[0] = pvB_A; B[1] = pvB_s; }
            else if (l == 30) {
                B[2] = vA_A; B[3] = vA_s; B[4] = vB_A; B[5] = vB_s;
                B[6] = pvA_A; B[7] = pvA_s; B[8] = pvB_A; B[9] = pvB_s;
            } else {
                B[10] = vA_A; B[11] = vA_s; B[12] = vB_A; B[13] = vB_s;
                B[14] = pvA_A; B[15] = pvA_s; B[16] = pvB_A; B[17] = pvB_s;
            }
        }
        __syncthreads();

#pragma unroll
        for (int s = 0; s < 4; s++) { cqA[s] = nqA[s]; cqB[s] = nqB[s]; }
    }

    // col 256 = warp 4, lane 7, cell B; value frozen at D[256][256]
    if (jB == 256) g_partial[b] = vB_A * 0.69314718055994531f - logf(vB_s);
}

// ---------------------------------------------------------------------------
// Kernel 3: mean over batches -> scalar output.
// ---------------------------------------------------------------------------
__global__ __launch_bounds__(256) void reduce_kernel(float* __restrict__ out) {
    __shared__ float sb[256];
    int t = threadIdx.x;
    sb[t] = g_partial[t];
    __syncthreads();
    for (int s = 128; s > 0; s >>= 1) {
        if (t < s) sb[t] += sb[t + s];
        __syncthreads();
    }
    if (t == 0) out[0] = sb[0] * (1.0f / BATCH);
}

extern "C" void kernel_launch(void* const* d_in, const int* in_sizes, int n_in,
                              void* d_out, int out_size) {
    (void)in_sizes; (void)n_in; (void)out_size;
    const float* x = (const float*)d_in[0];
    const float* y = (const float*)d_in[1];
    float* out = (float*)d_out;

    // swapped args -> transposed dist (dist^T[j-1][i-1])
    dist_kernel<<<BATCH, 256>>>(y, x);
    dtw_kernel<<<BATCH, NTD>>>();
    reduce_kernel<<<1, 256>>>(out);
}

// round 11
// speedup vs baseline: 1.2575x; 1.2575x over previous
#include <cuda_runtime.h>
#include <cuda_bf16.h>
#include <cstdint>

#define BATCH 256
#define NN 256
#define MM 256
#define DIM 32
#define BIGF 1e8f
#define LOG2E 1.4426950408889634f
#define LN2F 0.69314718055994531f
#define SBIG (1e8f * LOG2E)

// dist in 16x16-tiled layout: [b][tile=(r>>4)*16+(c>>4)][(r&15)*16+(c&15)]
__device__ float g_dist[BATCH * NN * MM];
__device__ float g_partial[BATCH];

__device__ __forceinline__ uint32_t smem_u32(const void* p) {
    uint32_t a;
    asm("{ .reg .u64 t; cvta.to.shared.u64 t, %1; cvt.u32.u64 %0, t; }" : "=r"(a) : "l"(p));
    return a;
}
__device__ __forceinline__ float ex2(float v) {
    float r;
    asm("ex2.approx.f32 %0, %1;" : "=f"(r) : "f"(v));
    return r;
}
__device__ __forceinline__ float lg2(float v) {
    float r;
    asm("lg2.approx.f32 %0, %1;" : "=f"(r) : "f"(v));
    return r;
}
__device__ __forceinline__ void ldmx4(uint32_t* r, uint32_t addr) {
    asm volatile("ldmatrix.sync.aligned.m8n8.x4.shared.b16 {%0,%1,%2,%3}, [%4];"
                 : "=r"(r[0]), "=r"(r[1]), "=r"(r[2]), "=r"(r[3]) : "r"(addr));
}
__device__ __forceinline__ void mma16816(float* c, const uint32_t* a, uint32_t b0,
                                         uint32_t b1) {
    asm volatile(
        "mma.sync.aligned.m16n8k16.row.col.f32.bf16.bf16.f32 "
        "{%0,%1,%2,%3}, {%4,%5,%6,%7}, {%8,%9}, {%0,%1,%2,%3};"
        : "+f"(c[0]), "+f"(c[1]), "+f"(c[2]), "+f"(c[3])
        : "r"(a[0]), "r"(a[1]), "r"(a[2]), "r"(a[3]), "r"(b0), "r"(b1));
}

#define PITCHB 80   // bytes per bf16 row (40 bf16); 8-row ldmatrix conflict-free

// ---------------------------------------------------------------------------
// Kernel 1: dist via mma.sync bf16, 16x16-tiled output (R6 version, 19.4us).
// ---------------------------------------------------------------------------
__global__ __launch_bounds__(256) void dist_kernel(const float* __restrict__ x,
                                                   const float* __restrict__ y) {
    __shared__ __align__(16) char xs[256 * PITCHB];
    __shared__ __align__(16) char ys[256 * PITCHB];
    __shared__ float x2s[256];
    __shared__ float y2s[256];

    const int b = blockIdx.x, t = threadIdx.x;
    const int w = t >> 5, lane = t & 31;
    const float* xr = x + ((size_t)b * NN + t) * DIM;
    const float* yr = y + ((size_t)b * MM + t) * DIM;

    {
        float sx = 0.f, sy = 0.f;
#pragma unroll
        for (int q = 0; q < 8; q++) {
            float4 v = *(const float4*)(xr + q * 4);
            sx = fmaf(v.x, v.x, fmaf(v.y, v.y, fmaf(v.z, v.z, fmaf(v.w, v.w, sx))));
            uint2 wv;
            asm("cvt.rn.bf16x2.f32 %0, %1, %2;" : "=r"(wv.x) : "f"(v.y), "f"(v.x));
            asm("cvt.rn.bf16x2.f32 %0, %1, %2;" : "=r"(wv.y) : "f"(v.w), "f"(v.z));
            *(uint2*)(xs + t * PITCHB + q * 8) = wv;
            float4 u = *(const float4*)(yr + q * 4);
            sy = fmaf(u.x, u.x, fmaf(u.y, u.y, fmaf(u.z, u.z, fmaf(u.w, u.w, sy))));
            uint2 uv;
            asm("cvt.rn.bf16x2.f32 %0, %1, %2;" : "=r"(uv.x) : "f"(u.y), "f"(u.x));
            asm("cvt.rn.bf16x2.f32 %0, %1, %2;" : "=r"(uv.y) : "f"(u.w), "f"(u.z));
            *(uint2*)(ys + t * PITCHB + q * 8) = uv;
        }
        x2s[t] = sx;
        y2s[t] = sy;
    }
    __syncthreads();

    const uint32_t xsb = smem_u32(xs), ysb = smem_u32(ys);
    const int i0w = w * 32;

    uint32_t afr[2][2][4];
    {
        int rowA = i0w + (lane & 15);
        uint32_t base = xsb + rowA * PITCHB + ((lane >> 4) << 4);
#pragma unroll
        for (int rt = 0; rt < 2; rt++)
#pragma unroll
            for (int ks = 0; ks < 2; ks++)
                ldmx4(afr[rt][ks], base + rt * 16 * PITCHB + ks * 32);
    }

    float* gb = g_dist + (size_t)b * (NN * MM);
    const int rsub = lane >> 2;
    const int cpair = 2 * (lane & 3);

    for (int cg = 0; cg < 16; cg++) {
        const int c0 = cg * 16;
        uint32_t bbase = ysb + (c0 + (lane & 7) + ((lane & 16) >> 1)) * PITCHB +
                         ((lane >> 3) & 1) * 16;
        uint32_t b_k0[4], b_k1[4];
        ldmx4(b_k0, bbase);
        ldmx4(b_k1, bbase + 32);

#pragma unroll
        for (int rt = 0; rt < 2; rt++) {
            float C0[4] = {0.f, 0.f, 0.f, 0.f};
            float C1[4] = {0.f, 0.f, 0.f, 0.f};
            mma16816(C0, afr[rt][0], b_k0[0], b_k0[1]);
            mma16816(C0, afr[rt][1], b_k1[0], b_k1[1]);
            mma16816(C1, afr[rt][0], b_k0[2], b_k0[3]);
            mma16816(C1, afr[rt][1], b_k1[2], b_k1[3]);

            const int r_lo = i0w + rt * 16 + rsub;
            const float x2lo = x2s[r_lo], x2hi = x2s[r_lo + 8];
            const int rowtile = ((r_lo >> 4) * 16 + cg) * 256;
            const int rin_lo = (r_lo & 15) << 4, rin_hi = ((r_lo + 8) & 15) << 4;
#pragma unroll
            for (int nt = 0; nt < 2; nt++) {
                const float* C = nt ? C1 : C0;
                const int cc = c0 + nt * 8 + cpair;
                float2 yy = *(const float2*)(y2s + cc);
                float2 olo, ohi;
                olo.x = fmaxf(fmaf(-2.f, C[0], x2lo + yy.x), 0.f);
                olo.y = fmaxf(fmaf(-2.f, C[1], x2lo + yy.y), 0.f);
                ohi.x = fmaxf(fmaf(-2.f, C[2], x2hi + yy.x), 0.f);
                ohi.y = fmaxf(fmaf(-2.f, C[3], x2hi + yy.y), 0.f);
                const int cin = nt * 8 + cpair;
                *(float2*)(gb + rowtile + rin_lo + cin) = olo;
                *(float2*)(gb + rowtile + rin_hi + cin) = ohi;
            }
        }
    }
}

// ---------------------------------------------------------------------------
// Kernel 2: wavefront DP, shuffle-group version (R6 structure), ONE batch per
// CTA at occupancy 2 (256 CTAs, 288 thr, 70KB smem -> 2 CTAs/SM, single wave;
// two independent DP chains interleave per SM to hide chain latency).
// Lane l of warp w owns column j = 29w + l - 2; lanes 0-2 redundant; 4
// diagonals per __syncthreads; neighbors via shfl_up; boundary (3 cols/warp)
// through double-buffered smem. Cells computed in log2 domain (raw ex2/lg2,
// dq folded with one fma) - final result scaled by ln2.
// ---------------------------------------------------------------------------
#define RINGF 16384                 // 4 slots x 4096 floats = 64KB
#define NT 288
#define SMEM_DP ((RINGF + 2 * 2 * 264) * 4)

__device__ __forceinline__ void issue_band(int T, const float* gb, uint32_t ringS, int t) {
    if (T > 30) return;
    int rt0 = T - 15 > 0 ? T - 15 : 0;
    int rt1 = T < 15 ? T : 15;
    int chunks = (rt1 - rt0 + 1) * 64;   // 16B chunks in this band
    uint32_t slotbase = ringS + (uint32_t)((T & 3) * 4096 * 4);
    for (int n = t; n < chunks; n += NT) {
        int tile = n >> 6, wi = n & 63;
        int rt = rt0 + tile;
        const float* g = gb + ((rt * 16 + (T - rt)) * 256 + wi * 4);
        uint32_t s = slotbase + (uint32_t)(((rt & 15) * 256 + wi * 4) * 4);
        asm volatile("cp.async.cg.shared.global [%0], [%1], 16;" :: "r"(s), "l"(g));
    }
}

__global__ __launch_bounds__(NT) void dtw_kernel() {
    extern __shared__ float sm[];
    float* ring = sm;
    float* bnd = sm + RINGF;   // [parity][v1/v0][264]
    const int b = blockIdx.x, t = threadIdx.x;
    const int w = t >> 5, l = t & 31;
    const int j = 29 * w + l - 2;          // owned column
    const int c = j - 1;                   // dist column index
    const bool cval = ((unsigned)c < 256u);
    const int ct = cval ? (c >> 4) : 0, cin = cval ? (c & 15) : 0;

    const float* gb = g_dist + (size_t)b * (NN * MM);
    uint32_t rs = smem_u32(ring);

    float v1 = SBIG;                          // diag p-1 (log2 domain)
    float v0 = (j == 0) ? 0.f : SBIG;         // diag p-2

    issue_band(0, gb, rs, t);
    asm volatile("cp.async.commit_group;");

    for (int g = 0; g < 128; ++g) {
        if ((g & 3) == 0) {
            int U = g >> 2;
            issue_band(U + 1, gb, rs, t);
            asm volatile("cp.async.commit_group;");
            asm volatile("cp.async.wait_group 1;");
        }
        __syncthreads();   // band visible + boundary exchange ordering

        if (g > 0 && l < 3 && w > 0) {   // refresh redundant lanes
            const float* B = bnd + ((g + 1) & 1) * 528;   // parity (g-1)&1
            v1 = B[j];
            v0 = B[264 + j];
        }

        const int p0 = 2 + 4 * g;
        // prefetch the 4 dist values (band already resident)
        float dq[4];
#pragma unroll
        for (int s = 0; s < 4; s++) {
            int r = p0 + s - j - 1;
            bool val = cval && ((unsigned)r < 256u);
            int rr = val ? r : 0;
            int off = ((((rr >> 4) + ct) & 3) << 12) + (((rr >> 4) & 15) << 8) +
                      ((rr & 15) << 4) + cin;
            dq[s] = val ? ring[off] : 0.f;
        }

        float dgp = __shfl_up_sync(0xffffffffu, v0, 1);

#pragma unroll
        for (int s = 0; s < 4; s++) {
            const int p = p0 + s;
            const int i = p - j;
            float lf = __shfl_up_sync(0xffffffffu, v1, 1);
            const bool val = cval && ((unsigned)(i - 1) < 256u);

            float up = v1, dg = dgp;
            float a = fminf(up, lf), bx = fmaxf(up, lf);
            float mn = fminf(a, dg);
            float mx = fmaxf(bx, dg);
            float md = fmaxf(a, fminf(bx, dg));       // exact median
            float ssum = 1.0f + ex2(mn - md) + ex2(mn - mx);
            float nv = fmaf(dq[s], LOG2E, mn) - lg2(ssum);
            nv = val ? nv : SBIG;

            if (p == NN + MM && j == MM)
                g_partial[b] = nv * LN2F;
            dgp = lf;
            v0 = v1;
            v1 = nv;
        }

        if (w < 8 && l >= 29) {   // publish boundary for next warp's lanes 0-2
            float* B = bnd + (g & 1) * 528;
            B[j] = v1;
            B[264 + j] = v0;
        }
    }
}

// ---------------------------------------------------------------------------
// Kernel 3: mean over batches -> scalar output.
// ---------------------------------------------------------------------------
__global__ __launch_bounds__(256) void reduce_kernel(float* __restrict__ out) {
    __shared__ float sb[256];
    int t = threadIdx.x;
    sb[t] = g_partial[t];
    __syncthreads();
    for (int s = 128; s > 0; s >>= 1) {
        if (t < s) sb[t] += sb[t + s];
        __syncthreads();
    }
    if (t == 0) out[0] = sb[0] * (1.0f / BATCH);
}

extern "C" void kernel_launch(void* const* d_in, const int* in_sizes, int n_in,
                              void* d_out, int out_size) {
    (void)in_sizes; (void)n_in; (void)out_size;
    const float* x = (const float*)d_in[0];
    const float* y = (const float*)d_in[1];
    float* out = (float*)d_out;

    cudaFuncSetAttribute(dtw_kernel, cudaFuncAttributeMaxDynamicSharedMemorySize,
                         SMEM_DP);

    dist_kernel<<<BATCH, 256>>>(x, y);
    dtw_kernel<<<BATCH, NT, SMEM_DP>>>();
    reduce_kernel<<<1, 256>>>(out);
}

// round 12
// speedup vs baseline: 1.4873x; 1.1827x over previous
#include <cuda_runtime.h>
#include <cuda_bf16.h>
#include <cstdint>

#define BATCH 256
#define NN 256
#define MM 256
#define DIM 32
#define BIGF 1e8f
#define LOG2E 1.4426950408889634f
#define LN2F 0.69314718055994531f
#define SBIG (1e8f * LOG2E)

// dist in 16x16-tiled layout: [b][tile=(r>>4)*16+(c>>4)][(r&15)*16+(c&15)]
__device__ float g_dist[BATCH * NN * MM];
__device__ float g_partial[BATCH];

__device__ __forceinline__ uint32_t smem_u32(const void* p) {
    uint32_t a;
    asm("{ .reg .u64 t; cvta.to.shared.u64 t, %1; cvt.u32.u64 %0, t; }" : "=r"(a) : "l"(p));
    return a;
}
__device__ __forceinline__ float ex2(float v) {
    float r;
    asm("ex2.approx.f32 %0, %1;" : "=f"(r) : "f"(v));
    return r;
}
__device__ __forceinline__ float lg2(float v) {
    float r;
    asm("lg2.approx.f32 %0, %1;" : "=f"(r) : "f"(v));
    return r;
}
__device__ __forceinline__ void ldmx4(uint32_t* r, uint32_t addr) {
    asm volatile("ldmatrix.sync.aligned.m8n8.x4.shared.b16 {%0,%1,%2,%3}, [%4];"
                 : "=r"(r[0]), "=r"(r[1]), "=r"(r[2]), "=r"(r[3]) : "r"(addr));
}
__device__ __forceinline__ void mma16816(float* c, const uint32_t* a, uint32_t b0,
                                         uint32_t b1) {
    asm volatile(
        "mma.sync.aligned.m16n8k16.row.col.f32.bf16.bf16.f32 "
        "{%0,%1,%2,%3}, {%4,%5,%6,%7}, {%8,%9}, {%0,%1,%2,%3};"
        : "+f"(c[0]), "+f"(c[1]), "+f"(c[2]), "+f"(c[3])
        : "r"(a[0]), "r"(a[1]), "r"(a[2]), "r"(a[3]), "r"(b0), "r"(b1));
}

#define PITCHB 80   // bytes per bf16 row (40 bf16); 8-row ldmatrix conflict-free

// ---------------------------------------------------------------------------
// Kernel 1: dist via mma.sync bf16, 16x16-tiled output. Grid = BATCH*2:
// each CTA does a 128-row half (8 warps x 16-row stripe) x 256 cols.
// Better SM packing than 1 CTA/batch (512 CTAs -> ~3.5/SM co-resident).
// ---------------------------------------------------------------------------
__global__ __launch_bounds__(256) void dist_kernel(const float* __restrict__ x,
                                                   const float* __restrict__ y) {
    __shared__ __align__(16) char xs[128 * PITCHB];
    __shared__ __align__(16) char ys[256 * PITCHB];
    __shared__ float x2s[128];
    __shared__ float y2s[256];

    const int bx = blockIdx.x, b = bx >> 1, half = bx & 1;
    const int t = threadIdx.x;
    const int w = t >> 5, lane = t & 31;

    // convert: threads 0-127 do x rows (of this half), all 256 do y rows
    if (t < 128) {
        const float* xr = x + ((size_t)b * NN + half * 128 + t) * DIM;
        float sx = 0.f;
#pragma unroll
        for (int q = 0; q < 8; q++) {
            float4 v = *(const float4*)(xr + q * 4);
            sx = fmaf(v.x, v.x, fmaf(v.y, v.y, fmaf(v.z, v.z, fmaf(v.w, v.w, sx))));
            uint2 wv;
            asm("cvt.rn.bf16x2.f32 %0, %1, %2;" : "=r"(wv.x) : "f"(v.y), "f"(v.x));
            asm("cvt.rn.bf16x2.f32 %0, %1, %2;" : "=r"(wv.y) : "f"(v.w), "f"(v.z));
            *(uint2*)(xs + t * PITCHB + q * 8) = wv;
        }
        x2s[t] = sx;
    }
    {
        const float* yr = y + ((size_t)b * MM + t) * DIM;
        float sy = 0.f;
#pragma unroll
        for (int q = 0; q < 8; q++) {
            float4 u = *(const float4*)(yr + q * 4);
            sy = fmaf(u.x, u.x, fmaf(u.y, u.y, fmaf(u.z, u.z, fmaf(u.w, u.w, sy))));
            uint2 uv;
            asm("cvt.rn.bf16x2.f32 %0, %1, %2;" : "=r"(uv.x) : "f"(u.y), "f"(u.x));
            asm("cvt.rn.bf16x2.f32 %0, %1, %2;" : "=r"(uv.y) : "f"(u.w), "f"(u.z));
            *(uint2*)(ys + t * PITCHB + q * 8) = uv;
        }
        y2s[t] = sy;
    }
    __syncthreads();

    const uint32_t xsb = smem_u32(xs), ysb = smem_u32(ys);
    const int i0w = w * 16;   // local 16-row stripe

    uint32_t afr[2][4];       // [ks][frag]
    {
        int rowA = i0w + (lane & 15);
        uint32_t base = xsb + rowA * PITCHB + ((lane >> 4) << 4);
#pragma unroll
        for (int ks = 0; ks < 2; ks++) ldmx4(afr[ks], base + ks * 32);
    }

    float* gb = g_dist + (size_t)b * (NN * MM);
    const int rsub = lane >> 2;
    const int cpair = 2 * (lane & 3);

    for (int cg = 0; cg < 16; cg++) {
        const int c0 = cg * 16;
        uint32_t bbase = ysb + (c0 + (lane & 7) + ((lane & 16) >> 1)) * PITCHB +
                         ((lane >> 3) & 1) * 16;
        uint32_t b_k0[4], b_k1[4];
        ldmx4(b_k0, bbase);
        ldmx4(b_k1, bbase + 32);

        float C0[4] = {0.f, 0.f, 0.f, 0.f};
        float C1[4] = {0.f, 0.f, 0.f, 0.f};
        mma16816(C0, afr[0], b_k0[0], b_k0[1]);
        mma16816(C0, afr[1], b_k1[0], b_k1[1]);
        mma16816(C1, afr[0], b_k0[2], b_k0[3]);
        mma16816(C1, afr[1], b_k1[2], b_k1[3]);

        const int rl = i0w + rsub;                 // local row
        const int r_lo = half * 128 + rl;          // global row
        const float x2lo = x2s[rl], x2hi = x2s[rl + 8];
        const int rowtile = ((r_lo >> 4) * 16 + cg) * 256;
        const int rin_lo = (r_lo & 15) << 4, rin_hi = ((r_lo + 8) & 15) << 4;
#pragma unroll
        for (int nt = 0; nt < 2; nt++) {
            const float* C = nt ? C1 : C0;
            const int cc = c0 + nt * 8 + cpair;
            float2 yy = *(const float2*)(y2s + cc);
            float2 olo, ohi;
            olo.x = fmaxf(fmaf(-2.f, C[0], x2lo + yy.x), 0.f);
            olo.y = fmaxf(fmaf(-2.f, C[1], x2lo + yy.y), 0.f);
            ohi.x = fmaxf(fmaf(-2.f, C[2], x2hi + yy.x), 0.f);
            ohi.y = fmaxf(fmaf(-2.f, C[3], x2hi + yy.y), 0.f);
            const int cin = nt * 8 + cpair;
            *(float2*)(gb + rowtile + rin_lo + cin) = olo;
            *(float2*)(gb + rowtile + rin_hi + cin) = ohi;
        }
    }
}

// ---------------------------------------------------------------------------
// Kernel 2: wavefront DP — R6 structure (best known: ILP-2, 128 CTAs x 288
// threads, 4 diagonals per barrier, shfl neighbors, redundant lanes), with
// cells computed in log2 domain (raw ex2/lg2 MUFU; dq folded by one fma).
// ---------------------------------------------------------------------------
#define RINGF 16384                 // floats per batch ring (4 slots x 4096)
#define NT 288
#define SMEM_DP ((2 * RINGF + 4 * 264) * 4)

__device__ __forceinline__ void issue_band(int T, const float* gb, uint32_t ringS, int t) {
    if (T > 30) return;
    int rt0 = T - 15 > 0 ? T - 15 : 0;
    int rt1 = T < 15 ? T : 15;
    int chunks = (rt1 - rt0 + 1) * 64;
    uint32_t slotbase = ringS + (uint32_t)((T & 3) * 4096 * 4);
    for (int n = t; n < chunks; n += NT) {
        int tile = n >> 6, wi = n & 63;
        int rt = rt0 + tile;
        const float* g = gb + ((rt * 16 + (T - rt)) * 256 + wi * 4);
        uint32_t s = slotbase + (uint32_t)(((rt & 15) * 256 + wi * 4) * 4);
        asm volatile("cp.async.cg.shared.global [%0], [%1], 16;" :: "r"(s), "l"(g));
    }
}

__global__ __launch_bounds__(NT) void dtw_kernel() {
    extern __shared__ float sm[];
    float* ring0 = sm;
    float* ring1 = sm + RINGF;
    float* bnd = sm + 2 * RINGF;   // 4 arrays of 264: b0v1, b0v0, b1v1, b1v0
    const int bb = blockIdx.x, t = threadIdx.x;
    const int w = t >> 5, l = t & 31;
    const int j = 29 * w + l - 2;          // owned column
    const int c = j - 1;                   // dist column index
    const bool cval = ((unsigned)c < 256u);
    const int ct = cval ? (c >> 4) : 0, cin = cval ? (c & 15) : 0;

    const float* gb0 = g_dist + (size_t)(2 * bb) * (NN * MM);
    const float* gb1 = g_dist + (size_t)(2 * bb + 1) * (NN * MM);
    uint32_t rs0 = smem_u32(ring0), rs1 = smem_u32(ring1);

    float v1_0 = SBIG, v0_0 = (j == 0) ? 0.f : SBIG;
    float v1_1 = SBIG, v0_1 = v0_0;

    // seed boundary for group 0
    if (w < 8 && l >= 29) {
        bnd[j] = v1_0; bnd[264 + j] = v0_0;
        bnd[528 + j] = v1_1; bnd[792 + j] = v0_1;
    }

    issue_band(0, gb0, rs0, t);
    issue_band(0, gb1, rs1, t);
    asm volatile("cp.async.commit_group;");

    for (int g = 0; g < 128; ++g) {
        if ((g & 3) == 0) {
            int U = g >> 2;
            issue_band(U + 1, gb0, rs0, t);
            issue_band(U + 1, gb1, rs1, t);
            asm volatile("cp.async.commit_group;");
            asm volatile("cp.async.wait_group 1;");
        }
        __syncthreads();   // band visible + boundary exchange

        if (l < 3 && w > 0) {   // refresh redundant lanes
            v1_0 = bnd[j]; v0_0 = bnd[264 + j];
            v1_1 = bnd[528 + j]; v0_1 = bnd[792 + j];
        }

        const int p0 = 2 + 4 * g;
        // prefetch 4 dist values per batch (off critical path)
        float dq0[4], dq1[4];
#pragma unroll
        for (int s = 0; s < 4; s++) {
            int r = p0 + s - j - 1;
            bool val = cval && ((unsigned)r < 256u);
            int rr = val ? r : 0;
            int off = ((((rr >> 4) + ct) & 3) << 12) + (((rr >> 4) & 15) << 8) +
                      ((rr & 15) << 4) + cin;
            dq0[s] = val ? ring0[off] : 0.f;
            dq1[s] = val ? ring1[off] : 0.f;
        }

        float dgp0 = __shfl_up_sync(0xffffffffu, v0_0, 1);
        float dgp1 = __shfl_up_sync(0xffffffffu, v0_1, 1);

#pragma unroll
        for (int s = 0; s < 4; s++) {
            const int p = p0 + s;
            const int i = p - j;
            float lf0 = __shfl_up_sync(0xffffffffu, v1_0, 1);
            float lf1 = __shfl_up_sync(0xffffffffu, v1_1, 1);
            const bool val = cval && ((unsigned)(i - 1) < 256u);

            float up0 = v1_0, dg0 = dgp0;
            float up1 = v1_1, dg1 = dgp1;
            float a0 = fminf(up0, lf0), b0 = fmaxf(up0, lf0);
            float mn0 = fminf(a0, dg0);
            float mx0 = fmaxf(b0, dg0);
            float md0 = fmaxf(a0, fminf(b0, dg0));
            float a1 = fminf(up1, lf1), b1 = fmaxf(up1, lf1);
            float mn1 = fminf(a1, dg1);
            float mx1 = fmaxf(b1, dg1);
            float md1 = fmaxf(a1, fminf(b1, dg1));
            float s0 = 1.0f + ex2(mn0 - md0) + ex2(mn0 - mx0);
            float s1 = 1.0f + ex2(mn1 - md1) + ex2(mn1 - mx1);
            float nv0 = fmaf(dq0[s], LOG2E, mn0) - lg2(s0);
            float nv1 = fmaf(dq1[s], LOG2E, mn1) - lg2(s1);
            nv0 = val ? nv0 : SBIG;
            nv1 = val ? nv1 : SBIG;

            if (p == NN + MM && j == MM) {
                g_partial[2 * bb] = nv0 * LN2F;
                g_partial[2 * bb + 1] = nv1 * LN2F;
            }
            dgp0 = lf0; dgp1 = lf1;
            v0_0 = v1_0; v1_0 = nv0;
            v0_1 = v1_1; v1_1 = nv1;
        }

        if (w < 8 && l >= 29) {   // publish boundary for next warp's lanes 0-2
            bnd[j] = v1_0; bnd[264 + j] = v0_0;
            bnd[528 + j] = v1_1; bnd[792 + j] = v0_1;
        }
    }
}

// ---------------------------------------------------------------------------
// Kernel 3: mean over batches -> scalar output.
// ---------------------------------------------------------------------------
__global__ __launch_bounds__(256) void reduce_kernel(float* __restrict__ out) {
    __shared__ float sb[256];
    int t = threadIdx.x;
    sb[t] = g_partial[t];
    __syncthreads();
    for (int s = 128; s > 0; s >>= 1) {
        if (t < s) sb[t] += sb[t + s];
        __syncthreads();
    }
    if (t == 0) out[0] = sb[0] * (1.0f / BATCH);
}

extern "C" void kernel_launch(void* const* d_in, const int* in_sizes, int n_in,
                              void* d_out, int out_size) {
    (void)in_sizes; (void)n_in; (void)out_size;
    const float* x = (const float*)d_in[0];
    const float* y = (const float*)d_in[1];
    float* out = (float*)d_out;

    cudaFuncSetAttribute(dtw_kernel, cudaFuncAttributeMaxDynamicSharedMemorySize,
                         SMEM_DP);

    dist_kernel<<<BATCH * 2, 256>>>(x, y);
    dtw_kernel<<<BATCH / 2, NT, SMEM_DP>>>();
    reduce_kernel<<<1, 256>>>(out);
}